// round 17
// baseline (speedup 1.0000x reference)
#include <cuda_runtime.h>
#include <cuda_bf16.h>
#include <cstdint>

#define BB 4096
#define TT 16
#define HH 768
#define AA 128
#define VV 16
#define LL 2
#define MTILE 32
#define NTILES_MAX 144
#define NCHK 6             // 768 / 128
#define KCH 128
#define STR2 272           // bytes per smem row: 128 bf16 (256B) + 16B pad
#define SA2 (MTILE * STR2)           // 8704
#define STAGE2 (SA2 + 128 * STR2)    // 43520
#define DYN_SMEM (3 * STAGE2)        // 130560 — 3-stage ring

// fused-prep grid partition (prep_x removed — x handled in main)
#define NWDT   (VV * (HH / 32))     // 384
#define NFOLD  (VV * 16)            // 256
#define NBIN   VV                   // 16
#define NPREP  (NWDT + NFOLD + NBIN)

// ---------------- device scratch ----------------
__device__ int g_counts[VV];
__device__ int g_bins[VV * BB];
__device__ float g_Wc2[VV * AA * LL];
__device__ float g_buc[VV * LL];
__device__ __align__(16) __nv_bfloat16 g_WdT[VV * AA * HH];

// ---------------- PTX helpers (sm_80+ baseline only) ----------------
__device__ __forceinline__ uint32_t smem_to_u32(const void* p) {
    uint32_t a;
    asm("{ .reg .u64 t; cvta.to.shared.u64 t, %1; cvt.u32.u64 %0, t; }"
        : "=r"(a) : "l"(p));
    return a;
}
#define CP_ASYNC16(dst, src) \
    asm volatile("cp.async.cg.shared.global [%0], [%1], 16;" :: "r"(dst), "l"(src) : "memory")
#define CP_COMMIT() asm volatile("cp.async.commit_group;" ::: "memory")
#define CP_WAITN(n) asm volatile("cp.async.wait_group %0;" :: "n"(n) : "memory")

__device__ __forceinline__ void ldsm4(uint32_t* r, uint32_t addr) {
    asm volatile("ldmatrix.sync.aligned.m8n8.x4.shared.b16 {%0,%1,%2,%3}, [%4];"
        : "=r"(r[0]), "=r"(r[1]), "=r"(r[2]), "=r"(r[3]) : "r"(addr));
}
__device__ __forceinline__ void mma16816(float* c, const uint32_t* a, const uint32_t* b) {
    asm volatile(
        "mma.sync.aligned.m16n8k16.row.col.f32.bf16.bf16.f32 "
        "{%0,%1,%2,%3}, {%4,%5,%6,%7}, {%8,%9}, {%0,%1,%2,%3};"
        : "+f"(c[0]), "+f"(c[1]), "+f"(c[2]), "+f"(c[3])
        : "r"(a[0]), "r"(a[1]), "r"(a[2]), "r"(a[3]), "r"(b[0]), "r"(b[1]));
}
__device__ __forceinline__ float gelu_fast(float x) {
    float x3 = x * x * x;
    float arg = 0.7978845608028654f * (x + 0.044715f * x3);
    float t;
    asm("tanh.approx.f32 %0, %1;" : "=f"(t) : "f"(arg));
    return 0.5f * x * (1.0f + t);
}

// ---------------- fused prep kernel (WdT + fold + bin) ----------------
__global__ void __launch_bounds__(256, 4)
va_prep(const float* __restrict__ Wc, const float* __restrict__ Wd,
        const float* __restrict__ Wu, const float* __restrict__ bu,
        const int* __restrict__ vids) {
    __shared__ __align__(16) char sbuf[32 * 130 * 2];
    const int bid  = blockIdx.x;
    const int tid  = threadIdx.x;
    const int warp = tid >> 5;
    const int lane = tid & 31;

    if (bid < NWDT) {
        // ---------- Wd transpose chunk ----------
        __nv_bfloat16* s = (__nv_bfloat16*)sbuf;
        const int v   = bid / (HH / 32);
        const int k0  = (bid % (HH / 32)) * 32;

        const float* base = Wd + (size_t)v * HH * AA + (size_t)k0 * AA;
        #pragma unroll
        for (int i = 0; i < 4; i++) {
            int idx4 = tid + i * 256;
            int k  = idx4 >> 5;
            int n4 = (idx4 & 31) * 4;
            float4 w = *(const float4*)(base + k * AA + n4);
            __nv_bfloat162 p0 = __floats2bfloat162_rn(w.x, w.y);
            __nv_bfloat162 p1 = __floats2bfloat162_rn(w.z, w.w);
            *reinterpret_cast<__nv_bfloat162*>(&s[k * 130 + n4])     = p0;
            *reinterpret_cast<__nv_bfloat162*>(&s[k * 130 + n4 + 2]) = p1;
        }
        __syncthreads();

        const int n     = tid >> 1;
        const int khalf = (tid & 1) * 16;
        __nv_bfloat16 tmp[16];
        #pragma unroll
        for (int e = 0; e < 16; e++)
            tmp[e] = s[(khalf + e) * 130 + n];
        uint4* dst = reinterpret_cast<uint4*>(g_WdT + ((size_t)v * AA + n) * HH + k0 + khalf);
        dst[0] = *reinterpret_cast<uint4*>(tmp);
        dst[1] = *reinterpret_cast<uint4*>(tmp + 8);
    } else if (bid < NWDT + NFOLD) {
        // ---------- fold Wc2 / buc ----------
        float* sWc = (float*)sbuf;
        const int idx = bid - NWDT;
        const int v   = idx >> 4;
        const int seg = idx & 15;

        for (int i = tid; i < HH * LL; i += 256) sWc[i] = Wc[i];
        __syncthreads();

        const int a = seg * 8 + warp;
        const float* row = Wu + ((size_t)v * AA + a) * HH;
        float s0 = 0.f, s1 = 0.f;
        #pragma unroll
        for (int it = 0; it < 6; it++) {
            int h = it * 128 + lane * 4;
            float4 w = *(const float4*)(row + h);
            s0 = fmaf(w.x, sWc[h + 0], s0);
            s0 = fmaf(w.y, sWc[h + 1], s0);
            s0 = fmaf(w.z, sWc[h + 2], s0);
            s0 = fmaf(w.w, sWc[h + 3], s0);
            s1 = fmaf(w.x, sWc[HH + h + 0], s1);
            s1 = fmaf(w.y, sWc[HH + h + 1], s1);
            s1 = fmaf(w.z, sWc[HH + h + 2], s1);
            s1 = fmaf(w.w, sWc[HH + h + 3], s1);
        }
        #pragma unroll
        for (int off = 16; off; off >>= 1) {
            s0 += __shfl_xor_sync(0xFFFFFFFFu, s0, off);
            s1 += __shfl_xor_sync(0xFFFFFFFFu, s1, off);
        }
        if (lane == 0) {
            g_Wc2[(v * AA + a) * 2 + 0] = s0;
            g_Wc2[(v * AA + a) * 2 + 1] = s1;
        }
        if (seg == 0 && warp == 0) {
            const float* brow = bu + (size_t)v * HH;
            float t0 = 0.f, t1 = 0.f;
            #pragma unroll
            for (int it = 0; it < 6; it++) {
                int h = it * 128 + lane * 4;
                float4 w = *(const float4*)(brow + h);
                t0 = fmaf(w.x, sWc[h + 0], t0);
                t0 = fmaf(w.y, sWc[h + 1], t0);
                t0 = fmaf(w.z, sWc[h + 2], t0);
                t0 = fmaf(w.w, sWc[h + 3], t0);
                t1 = fmaf(w.x, sWc[HH + h + 0], t1);
                t1 = fmaf(w.y, sWc[HH + h + 1], t1);
                t1 = fmaf(w.z, sWc[HH + h + 2], t1);
                t1 = fmaf(w.w, sWc[HH + h + 3], t1);
            }
            #pragma unroll
            for (int off = 16; off; off >>= 1) {
                t0 += __shfl_xor_sync(0xFFFFFFFFu, t0, off);
                t1 += __shfl_xor_sync(0xFFFFFFFFu, t1, off);
            }
            if (lane == 0) {
                g_buc[v * 2 + 0] = t0;
                g_buc[v * 2 + 1] = t1;
            }
        }
    } else {
        // ---------- bin: one block per variety ----------
        int* scnt = (int*)sbuf;
        const int v = bid - (NWDT + NFOLD);
        if (tid == 0) *scnt = 0;
        __syncthreads();
        for (int i = tid; i < BB; i += 256) {
            if (vids[i] == v) {
                int s = atomicAdd(scnt, 1);
                g_bins[v * BB + s] = i;
            }
        }
        __syncthreads();
        if (tid == 0) g_counts[v] = *scnt;
    }
}

// ---------------- main kernel: x fused (LDG fp32 -> bf16 STS + xc dot) ----------------
extern "C" __global__ void __launch_bounds__(256)
va_main_mma(const float* __restrict__ lh, const float* __restrict__ Wc,
            const float* __restrict__ bd, const float* __restrict__ bc,
            float* __restrict__ out) {
    extern __shared__ char dsm[];
    __shared__ int   sB[MTILE];
    __shared__ float sBd[128];
    __shared__ float sWc2[256];
    __shared__ float sWc[HH * LL];
    __shared__ float sXc[MTILE * 2];
    __shared__ float sRed[8 * MTILE * 2];

    const int tid  = threadIdx.x;
    const int warp = tid >> 5;     // 0..7 -> 16-col group
    const int lane = tid & 31;

    // ---- derive this CTA's (variety, segment) from counts inline ----
    const int t = blockIdx.x;
    int vv = -1, seg = 0, cnt = 0;
    {
        int nt = 0;
        #pragma unroll
        for (int vi = 0; vi < VV; vi++) {
            int c  = g_counts[vi];
            int tv = (c + MTILE - 1) >> 5;
            if (vv < 0 && t >= nt && t < nt + tv) { vv = vi; seg = t - nt; cnt = c; }
            nt += tv;
        }
    }
    if (vv < 0) return;
    const int row0 = seg * MTILE;

    if (tid < MTILE) {
        int gr = row0 + tid;
        sB[tid] = (gr < cnt) ? g_bins[vv * BB + gr] : -1;
    }
    if (tid < 128) sBd[tid] = bd[vv * AA + tid];
    sWc2[tid] = g_Wc2[vv * AA * LL + tid];
    for (int i = tid; i < HH * LL; i += 256) sWc[i] = Wc[i];
    __syncthreads();

    const uint32_t dynb = smem_to_u32(dsm);
    const __nv_bfloat16* wdtv = g_WdT + (size_t)vv * AA * HH;

    // ---- B cp.async plan: 8 16B loads per thread per chunk (128 rows x 256B) ----
    const __nv_bfloat16* srcB[8];
    uint32_t dstB[8];
    #pragma unroll
    for (int i = 0; i < 8; i++) {
        int idx = tid + i * 256;
        int row = idx >> 4, sg = idx & 15;
        srcB[i] = wdtv + (size_t)row * HH + sg * 8;
        dstB[i] = (uint32_t)(SA2 + row * STR2 + sg * 16);
    }

    // ---- A plan: thread -> (row = tid>>3, 16-col segment = tid&7) ----
    const int arow = tid >> 3;
    const int aseg = tid & 7;
    int brow = sB[arow];
    if (brow < 0) brow = 0;
    const float* xsrc = lh + (size_t)brow * TT * HH + aseg * 16;
    const uint32_t adst = arow * STR2 + aseg * 32;   // bf16 bytes within stage

    // ---- ldmatrix offsets ----
    uint32_t aOff[2];
    #pragma unroll
    for (int mf = 0; mf < 2; mf++)
        aOff[mf] = (uint32_t)((16 * mf + ((lane >> 3) & 1) * 8 + (lane & 7)) * STR2
                              + (lane >> 4) * 16);
    uint32_t bOff = (uint32_t)(SA2
                               + (16 * warp + (lane >> 4) * 8 + (lane & 7)) * STR2
                               + ((lane >> 3) & 1) * 16);

    float acc[2][2][4];
    #pragma unroll
    for (int mf = 0; mf < 2; mf++)
        #pragma unroll
        for (int nf = 0; nf < 2; nf++)
            #pragma unroll
            for (int e = 0; e < 4; e++) acc[mf][nf][e] = 0.f;

    float xc0 = 0.f, xc1 = 0.f;
    float4 xr[2][4];   // double-buffered A registers (chunk parity)

    // ---- prologue: B chunks 0,1 via cp.async; A chunks 0,1 via LDG ----
    #pragma unroll
    for (int s = 0; s < 2; s++) {
        uint32_t base = dynb + s * STAGE2;
        #pragma unroll
        for (int i = 0; i < 8; i++)
            CP_ASYNC16(base + dstB[i], srcB[i] + s * KCH);
        CP_COMMIT();
    }
    #pragma unroll
    for (int s = 0; s < 2; s++)
        #pragma unroll
        for (int q = 0; q < 4; q++)
            xr[s][q] = *(const float4*)(xsrc + s * KCH + q * 4);

    // ---- mainloop: 3-stage ring (B), reg double-buffer (A) ----
    #pragma unroll
    for (int c = 0; c < NCHK; c++) {
        const int stc = c % 3;
        if (c + 2 < NCHK) {
            uint32_t base = dynb + ((c + 2) % 3) * STAGE2;
            const int koff = (c + 2) * KCH;
            #pragma unroll
            for (int i = 0; i < 8; i++)
                CP_ASYNC16(base + dstB[i], srcB[i] + koff);
            CP_COMMIT();
            CP_WAITN(2);
        } else if (c + 1 < NCHK) {
            CP_WAITN(1);
        } else {
            CP_WAITN(0);
        }

        // ---- convert this chunk's A regs -> bf16 smem; accumulate xc ----
        {
            const int p = c & 1;
            const int colb = c * KCH + aseg * 16;
            __nv_bfloat16 hb[16];
            #pragma unroll
            for (int q = 0; q < 4; q++) {
                float4 v = xr[p][q];
                int cb = colb + q * 4;
                xc0 = fmaf(v.x, sWc[cb + 0], xc0);
                xc0 = fmaf(v.y, sWc[cb + 1], xc0);
                xc0 = fmaf(v.z, sWc[cb + 2], xc0);
                xc0 = fmaf(v.w, sWc[cb + 3], xc0);
                xc1 = fmaf(v.x, sWc[HH + cb + 0], xc1);
                xc1 = fmaf(v.y, sWc[HH + cb + 1], xc1);
                xc1 = fmaf(v.z, sWc[HH + cb + 2], xc1);
                xc1 = fmaf(v.w, sWc[HH + cb + 3], xc1);
                __nv_bfloat162 p0 = __floats2bfloat162_rn(v.x, v.y);
                __nv_bfloat162 p1 = __floats2bfloat162_rn(v.z, v.w);
                *reinterpret_cast<__nv_bfloat162*>(&hb[q * 4 + 0]) = p0;
                *reinterpret_cast<__nv_bfloat162*>(&hb[q * 4 + 2]) = p1;
            }
            uint32_t a0 = dynb + stc * STAGE2 + adst;
            *reinterpret_cast<uint4*>(dsm + (a0 - dynb) + stc * 0) =
                *reinterpret_cast<uint4*>(hb);          // first 8 bf16
            *reinterpret_cast<uint4*>(dsm + (a0 - dynb) + 16) =
                *reinterpret_cast<uint4*>(hb + 8);      // next 8 bf16
        }
        __syncthreads();

        // ---- prefetch A regs for chunk c+2 (hidden under compute) ----
        if (c + 2 < NCHK) {
            const int p = c & 1;
            #pragma unroll
            for (int q = 0; q < 4; q++)
                xr[p][q] = *(const float4*)(xsrc + (c + 2) * KCH + q * 4);
        }

        const uint32_t base = dynb + stc * STAGE2;
        #pragma unroll
        for (int step = 0; step < 8; step++) {
            const uint32_t kb = step * 32;
            uint32_t af[2][4], bf[4];
            ldsm4(af[0], base + aOff[0] + kb);
            ldsm4(af[1], base + aOff[1] + kb);
            ldsm4(bf, base + bOff + kb);
            #pragma unroll
            for (int mf = 0; mf < 2; mf++) {
                mma16816(acc[mf][0], af[mf], &bf[0]);
                mma16816(acc[mf][1], af[mf], &bf[2]);
            }
        }
        __syncthreads();
    }

    // ---- reduce xc across the 8 segment-threads of each row ----
    xc0 += __shfl_xor_sync(0xFFFFFFFFu, xc0, 1);
    xc0 += __shfl_xor_sync(0xFFFFFFFFu, xc0, 2);
    xc0 += __shfl_xor_sync(0xFFFFFFFFu, xc0, 4);
    xc1 += __shfl_xor_sync(0xFFFFFFFFu, xc1, 1);
    xc1 += __shfl_xor_sync(0xFFFFFFFFu, xc1, 2);
    xc1 += __shfl_xor_sync(0xFFFFFFFFu, xc1, 4);
    if (aseg == 0) {
        sXc[arow * 2 + 0] = xc0;
        sXc[arow * 2 + 1] = xc1;
    }

    // ---- epilogue: gelu + folded head ----
    float rp[2][2][2];   // [mf][hh][l]
    #pragma unroll
    for (int mf = 0; mf < 2; mf++)
        #pragma unroll
        for (int hh = 0; hh < 2; hh++) { rp[mf][hh][0] = 0.f; rp[mf][hh][1] = 0.f; }

    #pragma unroll
    for (int mf = 0; mf < 2; mf++)
        #pragma unroll
        for (int nf = 0; nf < 2; nf++) {
            int col0 = 16 * warp + 8 * nf + 2 * (lane & 3);
            #pragma unroll
            for (int e = 0; e < 4; e++) {
                int col = col0 + (e & 1);
                int hh  = e >> 1;
                float h = gelu_fast(acc[mf][nf][e] + sBd[col]);
                rp[mf][hh][0] = fmaf(h, sWc2[col * 2 + 0], rp[mf][hh][0]);
                rp[mf][hh][1] = fmaf(h, sWc2[col * 2 + 1], rp[mf][hh][1]);
            }
        }

    #pragma unroll
    for (int mf = 0; mf < 2; mf++)
        #pragma unroll
        for (int hh = 0; hh < 2; hh++)
            #pragma unroll
            for (int l = 0; l < 2; l++) {
                float s = rp[mf][hh][l];
                s += __shfl_xor_sync(0xFFFFFFFFu, s, 1);
                s += __shfl_xor_sync(0xFFFFFFFFu, s, 2);
                rp[mf][hh][l] = s;
            }

    if ((lane & 3) == 0) {
        int rbase = lane >> 2;
        #pragma unroll
        for (int mf = 0; mf < 2; mf++)
            #pragma unroll
            for (int hh = 0; hh < 2; hh++) {
                int row = 16 * mf + 8 * hh + rbase;
                sRed[(warp * MTILE + row) * 2 + 0] = rp[mf][hh][0];
                sRed[(warp * MTILE + row) * 2 + 1] = rp[mf][hh][1];
            }
    }
    __syncthreads();

    if (tid < MTILE * LL) {
        int row = tid >> 1;
        int l   = tid & 1;
        int b   = sB[row];
        if (b >= 0) {
            float s = sXc[row * 2 + l] + g_buc[vv * 2 + l] + __ldg(bc + l);
            #pragma unroll
            for (int w = 0; w < 8; w++)
                s += sRed[(w * MTILE + row) * 2 + l];
            out[b * 2 + l] = s;
        }
    }
}

extern "C" void kernel_launch(void* const* d_in, const int* in_sizes, int n_in,
                              void* d_out, int out_size) {
    const float* lh   = (const float*)d_in[0];
    const int*   vids = (const int*)d_in[2];
    const float* Wd   = (const float*)d_in[3];
    const float* bd   = (const float*)d_in[4];
    const float* Wu   = (const float*)d_in[5];
    const float* bu   = (const float*)d_in[6];
    const float* Wc   = (const float*)d_in[7];
    const float* bc   = (const float*)d_in[8];
    float* out = (float*)d_out;

    cudaFuncSetAttribute(va_main_mma, cudaFuncAttributeMaxDynamicSharedMemorySize, DYN_SMEM);

    va_prep<<<NPREP, 256>>>(Wc, Wd, Wu, bu, vids);
    va_main_mma<<<NTILES_MAX, 256, DYN_SMEM>>>(lh, Wc, bd, bc, out);
}